// round 1
// baseline (speedup 1.0000x reference)
#include <cuda_runtime.h>
#include <cuda_bf16.h>
#include <math.h>

#define T_SEQ 2048
#define D_MODEL 1024
#define N_HEADS 16
#define HEAD_DIM 64
#define FFN_DIM 4096

// ---------------- scratch (no allocations allowed) ----------------
__device__ float g_xn[T_SEQ * D_MODEL];     // x_norm (reused for LN2 output)
__device__ float g_q[T_SEQ * D_MODEL];
__device__ float g_k[T_SEQ * D_MODEL];
__device__ float g_v[T_SEQ * D_MODEL];
__device__ float g_attn[T_SEQ * D_MODEL];
__device__ float g_x1[T_SEQ * D_MODEL];     // x + attn_out
__device__ float g_h[T_SEQ * FFN_DIM];      // FFN hidden

// ---------------- LayerNorm: one block per row ----------------
__global__ void ln_kernel(const float* __restrict__ x, const float* __restrict__ g,
                          const float* __restrict__ b, float* __restrict__ y) {
    int row = blockIdx.x;
    const float* xr = x + row * D_MODEL;
    float s = 0.f, s2 = 0.f;
    for (int c = threadIdx.x; c < D_MODEL; c += 256) {
        float v = xr[c];
        s += v; s2 += v * v;
    }
    __shared__ float red0[32], red1[32];
    #pragma unroll
    for (int o = 16; o > 0; o >>= 1) {
        s  += __shfl_down_sync(0xffffffffu, s, o);
        s2 += __shfl_down_sync(0xffffffffu, s2, o);
    }
    int w = threadIdx.x >> 5, l = threadIdx.x & 31;
    if (l == 0) { red0[w] = s; red1[w] = s2; }
    __syncthreads();
    if (w == 0) {
        s  = (l < 8) ? red0[l] : 0.f;
        s2 = (l < 8) ? red1[l] : 0.f;
        #pragma unroll
        for (int o = 4; o > 0; o >>= 1) {
            s  += __shfl_down_sync(0xffffffffu, s, o);
            s2 += __shfl_down_sync(0xffffffffu, s2, o);
        }
        if (l == 0) { red0[0] = s; red1[0] = s2; }
    }
    __syncthreads();
    float mu  = red0[0] * (1.f / D_MODEL);
    float var = red1[0] * (1.f / D_MODEL) - mu * mu;
    float inv = rsqrtf(var + 1e-5f);
    float* yr = y + row * D_MODEL;
    for (int c = threadIdx.x; c < D_MODEL; c += 256)
        yr[c] = (xr[c] - mu) * inv * g[c] + b[c];
}

// ---------------- generic GEMM: C = act(A@B + bias) (+ residual) ----------------
// A: MxK row-major, B: KxN row-major. BM=BN=128, BK=16, 256 threads, 8x8 per thread.
#define BM 128
#define BN 128
#define BK 16
#define TM 8
#define TN 8

template<int ACT, bool HAS_RES>
__global__ void __launch_bounds__(256, 2)
gemm_kernel(const float* __restrict__ A, const float* __restrict__ B,
            const float* __restrict__ bias, const float* __restrict__ Res,
            float* __restrict__ C, int M, int N, int K) {
    __shared__ float As[BK][BM];   // transposed A tile
    __shared__ float Bs[BK][BN];

    int tid = threadIdx.x;
    int blockRow = blockIdx.y * BM;
    int blockCol = blockIdx.x * BN;

    int aRow  = tid >> 2;           // 0..63
    int aCol4 = (tid & 3) << 2;     // 0,4,8,12
    int bRow  = tid >> 5;           // 0..7
    int bCol4 = (tid & 31) << 2;    // 0..124

    int ty = tid >> 4, tx = tid & 15;
    float acc[TM][TN] = {};
    float ra[TM], rb[TN];

    for (int k0 = 0; k0 < K; k0 += BK) {
        #pragma unroll
        for (int s = 0; s < 2; ++s) {
            int r = aRow + s * 64;
            float4 v = *reinterpret_cast<const float4*>(&A[(size_t)(blockRow + r) * K + k0 + aCol4]);
            As[aCol4 + 0][r] = v.x; As[aCol4 + 1][r] = v.y;
            As[aCol4 + 2][r] = v.z; As[aCol4 + 3][r] = v.w;
        }
        #pragma unroll
        for (int s = 0; s < 2; ++s) {
            int r = bRow + s * 8;
            float4 v = *reinterpret_cast<const float4*>(&B[(size_t)(k0 + r) * N + blockCol + bCol4]);
            *reinterpret_cast<float4*>(&Bs[r][bCol4]) = v;
        }
        __syncthreads();
        #pragma unroll
        for (int k = 0; k < BK; ++k) {
            #pragma unroll
            for (int i = 0; i < TM; ++i) ra[i] = As[k][ty * TM + i];
            #pragma unroll
            for (int j = 0; j < TN; ++j) rb[j] = Bs[k][tx * TN + j];
            #pragma unroll
            for (int i = 0; i < TM; ++i)
                #pragma unroll
                for (int j = 0; j < TN; ++j)
                    acc[i][j] = fmaf(ra[i], rb[j], acc[i][j]);
        }
        __syncthreads();
    }

    #pragma unroll
    for (int i = 0; i < TM; ++i) {
        int row = blockRow + ty * TM + i;
        #pragma unroll
        for (int j = 0; j < TN; ++j) {
            int col = blockCol + tx * TN + j;
            float v = acc[i][j] + bias[col];
            if (ACT == 1) v = 0.5f * v * (1.0f + erff(v * 0.7071067811865475f));
            if (HAS_RES) v += Res[(size_t)row * N + col];
            C[(size_t)row * N + col] = v;
        }
    }
}

// ---------------- flash attention (fp32, causal, analytic ALiBi) ----------------
// grid: (T/64, H). 256 threads. 64x64 q tile, streams 64-row K/V blocks.
// smem: Qs[64][65], KVs[64][65] (K then reused for V), Ss[64][65], stats.
__global__ void __launch_bounds__(256, 2)
attn_kernel(const float* __restrict__ Q, const float* __restrict__ K,
            const float* __restrict__ V, float* __restrict__ O) {
    extern __shared__ float sm[];
    float (*Qs)[65]  = (float(*)[65])sm;
    float (*KVs)[65] = (float(*)[65])(sm + 64 * 65);
    float (*Ss)[65]  = (float(*)[65])(sm + 2 * 64 * 65);
    float* m_sh = sm + 3 * 64 * 65;
    float* l_sh = m_sh + 64;
    float* a_sh = l_sh + 64;

    int qb = blockIdx.x, h = blockIdx.y;
    int tid = threadIdx.x;
    int r0 = (tid >> 4) * 4;
    int c0 = (tid & 15) * 4;

    // load Q tile (rows qb*64.., cols h*64..)
    for (int i = tid; i < 64 * 16; i += 256) {
        int r = i >> 4, c4 = (i & 15) << 2;
        float4 v = *reinterpret_cast<const float4*>(&Q[(size_t)(qb * 64 + r) * D_MODEL + h * 64 + c4]);
        Qs[r][c4] = v.x; Qs[r][c4 + 1] = v.y; Qs[r][c4 + 2] = v.z; Qs[r][c4 + 3] = v.w;
    }
    if (tid < 64) { m_sh[tid] = -1e30f; l_sh[tid] = 0.f; }

    float o_acc[4][4] = {};
    float slope = exp2f(-0.5f * (float)(h + 1));

    for (int kb = 0; kb <= qb; ++kb) {
        __syncthreads();   // prior iter's PV (reads KVs/Ss) done; Q-load done on iter 0
        for (int i = tid; i < 64 * 16; i += 256) {
            int r = i >> 4, c4 = (i & 15) << 2;
            float4 v = *reinterpret_cast<const float4*>(&K[(size_t)(kb * 64 + r) * D_MODEL + h * 64 + c4]);
            KVs[r][c4] = v.x; KVs[r][c4 + 1] = v.y; KVs[r][c4 + 2] = v.z; KVs[r][c4 + 3] = v.w;
        }
        __syncthreads();

        // S = Q @ K^T
        float s_acc[4][4] = {};
        #pragma unroll
        for (int d = 0; d < 64; ++d) {
            float qv[4], kv[4];
            #pragma unroll
            for (int i = 0; i < 4; ++i) qv[i] = Qs[r0 + i][d];
            #pragma unroll
            for (int j = 0; j < 4; ++j) kv[j] = KVs[c0 + j][d];
            #pragma unroll
            for (int i = 0; i < 4; ++i)
                #pragma unroll
                for (int j = 0; j < 4; ++j)
                    s_acc[i][j] = fmaf(qv[i], kv[j], s_acc[i][j]);
        }
        // scale + ALiBi + causal, store to Ss
        #pragma unroll
        for (int i = 0; i < 4; ++i) {
            int qq = qb * 64 + r0 + i;
            #pragma unroll
            for (int j = 0; j < 4; ++j) {
                int kk = kb * 64 + c0 + j;
                float v = s_acc[i][j] * 0.125f + slope * (float)(kk - qq);
                Ss[r0 + i][c0 + j] = (kk <= qq) ? v : -1e30f;
            }
        }
        __syncthreads();

        // online softmax (one thread per row)
        if (tid < 64) {
            float mo = m_sh[tid];
            float mx = mo;
            #pragma unroll 8
            for (int c = 0; c < 64; ++c) mx = fmaxf(mx, Ss[tid][c]);
            float alpha = __expf(mo - mx);
            float sum = 0.f;
            #pragma unroll 8
            for (int c = 0; c < 64; ++c) {
                float p = __expf(Ss[tid][c] - mx);
                Ss[tid][c] = p;
                sum += p;
            }
            m_sh[tid] = mx;
            l_sh[tid] = l_sh[tid] * alpha + sum;
            a_sh[tid] = alpha;
        }
        __syncthreads();

        // rescale accumulators
        #pragma unroll
        for (int i = 0; i < 4; ++i) {
            float a = a_sh[r0 + i];
            #pragma unroll
            for (int j = 0; j < 4; ++j) o_acc[i][j] *= a;
        }
        // load V into KVs (S-compute readers of KVs are past the post-Ss barrier)
        for (int i = tid; i < 64 * 16; i += 256) {
            int r = i >> 4, c4 = (i & 15) << 2;
            float4 v = *reinterpret_cast<const float4*>(&V[(size_t)(kb * 64 + r) * D_MODEL + h * 64 + c4]);
            KVs[r][c4] = v.x; KVs[r][c4 + 1] = v.y; KVs[r][c4 + 2] = v.z; KVs[r][c4 + 3] = v.w;
        }
        __syncthreads();

        // O += P @ V
        #pragma unroll
        for (int k = 0; k < 64; ++k) {
            float pv[4], vv[4];
            #pragma unroll
            for (int i = 0; i < 4; ++i) pv[i] = Ss[r0 + i][k];
            #pragma unroll
            for (int j = 0; j < 4; ++j) vv[j] = KVs[k][c0 + j];
            #pragma unroll
            for (int i = 0; i < 4; ++i)
                #pragma unroll
                for (int j = 0; j < 4; ++j)
                    o_acc[i][j] = fmaf(pv[i], vv[j], o_acc[i][j]);
        }
    }
    __syncthreads();

    #pragma unroll
    for (int i = 0; i < 4; ++i) {
        float inv = 1.f / l_sh[r0 + i];
        int row = qb * 64 + r0 + i;
        #pragma unroll
        for (int j = 0; j < 4; ++j)
            O[(size_t)row * D_MODEL + h * 64 + c0 + j] = o_acc[i][j] * inv;
    }
}

// ---------------- launch ----------------
extern "C" void kernel_launch(void* const* d_in, const int* in_sizes, int n_in,
                              void* d_out, int out_size) {
    const float* x   = (const float*)d_in[0];
    // d_in[1] = causal_mask (unused, analytic)
    // d_in[2] = alibi_bias  (unused, analytic)
    const float* wq  = (const float*)d_in[3];
    const float* bq  = (const float*)d_in[4];
    const float* wk  = (const float*)d_in[5];
    const float* bk  = (const float*)d_in[6];
    const float* wv  = (const float*)d_in[7];
    const float* bv  = (const float*)d_in[8];
    const float* wo  = (const float*)d_in[9];
    const float* bo  = (const float*)d_in[10];
    const float* w1  = (const float*)d_in[11];
    const float* b1  = (const float*)d_in[12];
    const float* w2  = (const float*)d_in[13];
    const float* b2  = (const float*)d_in[14];
    const float* g1  = (const float*)d_in[15];
    const float* be1 = (const float*)d_in[16];
    const float* g2  = (const float*)d_in[17];
    const float* be2 = (const float*)d_in[18];
    float* out = (float*)d_out;

    float *p_xn, *p_q, *p_k, *p_v, *p_attn, *p_x1, *p_h;
    cudaGetSymbolAddress((void**)&p_xn,   g_xn);
    cudaGetSymbolAddress((void**)&p_q,    g_q);
    cudaGetSymbolAddress((void**)&p_k,    g_k);
    cudaGetSymbolAddress((void**)&p_v,    g_v);
    cudaGetSymbolAddress((void**)&p_attn, g_attn);
    cudaGetSymbolAddress((void**)&p_x1,   g_x1);
    cudaGetSymbolAddress((void**)&p_h,    g_h);

    int attn_smem = (3 * 64 * 65 + 3 * 64) * (int)sizeof(float);
    cudaFuncSetAttribute(attn_kernel, cudaFuncAttributeMaxDynamicSharedMemorySize, attn_smem);

    // LN1
    ln_kernel<<<T_SEQ, 256>>>(x, g1, be1, p_xn);

    // Q,K,V projections
    dim3 gD(D_MODEL / BN, T_SEQ / BM);
    gemm_kernel<0, false><<<gD, 256>>>(p_xn, wq, bq, nullptr, p_q, T_SEQ, D_MODEL, D_MODEL);
    gemm_kernel<0, false><<<gD, 256>>>(p_xn, wk, bk, nullptr, p_k, T_SEQ, D_MODEL, D_MODEL);
    gemm_kernel<0, false><<<gD, 256>>>(p_xn, wv, bv, nullptr, p_v, T_SEQ, D_MODEL, D_MODEL);

    // attention
    attn_kernel<<<dim3(T_SEQ / 64, N_HEADS), 256, attn_smem>>>(p_q, p_k, p_v, p_attn);

    // O projection + residual
    gemm_kernel<0, true><<<gD, 256>>>(p_attn, wo, bo, x, p_x1, T_SEQ, D_MODEL, D_MODEL);

    // LN2
    ln_kernel<<<T_SEQ, 256>>>(p_x1, g2, be2, p_xn);

    // FFN1 + exact GELU
    dim3 gF1(FFN_DIM / BN, T_SEQ / BM);
    gemm_kernel<1, false><<<gF1, 256>>>(p_xn, w1, b1, nullptr, p_h, T_SEQ, FFN_DIM, D_MODEL);

    // FFN2 + residual -> out
    gemm_kernel<0, true><<<gD, 256>>>(p_h, w2, b2, p_x1, out, T_SEQ, D_MODEL, FFN_DIM);
}

// round 3
// speedup vs baseline: 2.0310x; 2.0310x over previous
#include <cuda_runtime.h>
#include <cuda_bf16.h>
#include <math.h>
#include <stdint.h>

#define T_SEQ 2048
#define D_MODEL 1024
#define N_HEADS 16
#define HEAD_DIM 64
#define FFN_DIM 4096

// ---------------- scratch ----------------
__device__ float g_xn[T_SEQ * D_MODEL];
__device__ float g_q[T_SEQ * D_MODEL];
__device__ float g_k[T_SEQ * D_MODEL];
__device__ float g_v[T_SEQ * D_MODEL];
__device__ float g_attn[T_SEQ * D_MODEL];
__device__ float g_x1[T_SEQ * D_MODEL];
__device__ float g_h[T_SEQ * FFN_DIM];

// ---------------- helpers ----------------
__device__ __forceinline__ uint32_t smem_u32(const void* p) {
    uint32_t a;
    asm("{ .reg .u64 t; cvta.to.shared.u64 t, %1; cvt.u32.u64 %0, t; }" : "=r"(a) : "l"(p));
    return a;
}
__device__ __forceinline__ void cp16(uint32_t s, const void* g) {
    asm volatile("cp.async.cg.shared.global [%0], [%1], 16;" :: "r"(s), "l"(g));
}
#define CP_COMMIT() asm volatile("cp.async.commit_group;" ::: "memory")
#define CP_WAIT(n)  asm volatile("cp.async.wait_group %0;" :: "n"(n) : "memory")

__device__ __forceinline__ void mma_tf32(float* d, const uint32_t* a, const uint32_t* b) {
    asm volatile(
        "mma.sync.aligned.m16n8k8.row.col.f32.tf32.tf32.f32 "
        "{%0,%1,%2,%3}, {%4,%5,%6,%7}, {%8,%9}, {%0,%1,%2,%3};"
        : "+f"(d[0]), "+f"(d[1]), "+f"(d[2]), "+f"(d[3])
        : "r"(a[0]), "r"(a[1]), "r"(a[2]), "r"(a[3]), "r"(b[0]), "r"(b[1]));
}

// ---------------- LayerNorm ----------------
__global__ void ln_kernel(const float* __restrict__ x, const float* __restrict__ g,
                          const float* __restrict__ b, float* __restrict__ y) {
    int row = blockIdx.x;
    const float* xr = x + row * D_MODEL;
    float s = 0.f, s2 = 0.f;
    for (int c = threadIdx.x; c < D_MODEL; c += 256) {
        float v = xr[c];
        s += v; s2 += v * v;
    }
    __shared__ float red0[32], red1[32];
    #pragma unroll
    for (int o = 16; o > 0; o >>= 1) {
        s  += __shfl_down_sync(0xffffffffu, s, o);
        s2 += __shfl_down_sync(0xffffffffu, s2, o);
    }
    int w = threadIdx.x >> 5, l = threadIdx.x & 31;
    if (l == 0) { red0[w] = s; red1[w] = s2; }
    __syncthreads();
    if (w == 0) {
        s  = (l < 8) ? red0[l] : 0.f;
        s2 = (l < 8) ? red1[l] : 0.f;
        #pragma unroll
        for (int o = 4; o > 0; o >>= 1) {
            s  += __shfl_down_sync(0xffffffffu, s, o);
            s2 += __shfl_down_sync(0xffffffffu, s2, o);
        }
        if (l == 0) { red0[0] = s; red1[0] = s2; }
    }
    __syncthreads();
    float mu  = red0[0] * (1.f / D_MODEL);
    float var = red1[0] * (1.f / D_MODEL) - mu * mu;
    float inv = rsqrtf(var + 1e-5f);
    float* yr = y + row * D_MODEL;
    for (int c = threadIdx.x; c < D_MODEL; c += 256)
        yr[c] = (xr[c] - mu) * inv * g[c] + b[c];
}

// ---------------- tf32 mma.sync GEMM ----------------
// C[M,N] = act(A[M,K] @ W[K,N] + bias) (+ Res). Tile 128x128x32, 8 warps (4x2),
// each warp 32x64 via m16n8k8. cp.async double buffer.
// SMEM per stage: A 128 rows x stride 36 floats (144B), B 32 rows x stride 136 floats (544B).
#define A_STRIDE 36
#define B_STRIDE 136
#define A_BYTES (128 * A_STRIDE * 4)       // 18432
#define B_BYTES (32 * B_STRIDE * 4)        // 17408
#define STAGE_BYTES (A_BYTES + B_BYTES)    // 35840
#define SMEM_GEMM (2 * STAGE_BYTES)        // 71680

template<int ACT, bool HAS_RES>
__global__ void __launch_bounds__(256, 2)
mma_gemm(const float* __restrict__ A,
         const float* __restrict__ W0, const float* __restrict__ W1, const float* __restrict__ W2,
         const float* __restrict__ b0, const float* __restrict__ b1, const float* __restrict__ b2,
         const float* __restrict__ Res,
         float* __restrict__ C0, float* __restrict__ C1, float* __restrict__ C2,
         int N, int K) {
    extern __shared__ char smem[];
    const int z = blockIdx.z;
    const float* W    = (z == 0) ? W0 : (z == 1) ? W1 : W2;
    const float* bias = (z == 0) ? b0 : (z == 1) ? b1 : b2;
    float* C          = (z == 0) ? C0 : (z == 1) ? C1 : C2;

    const int m0 = blockIdx.y * 128;
    const int n0 = blockIdx.x * 128;
    const int tid = threadIdx.x;
    const int wid = tid >> 5, lane = tid & 31;
    const int wrow = wid & 3;          // 4 warp rows x 32
    const int wcol = wid >> 2;         // 2 warp cols x 64
    const int lr = lane >> 2;          // 0..7
    const int lc = lane & 3;           // 0..3

    const uint32_t sbase = smem_u32(smem);

    // per-thread cp.async targets
    // A: 1024 float4 total, 4/thread: flat f = tid*4+j, row=f>>3, c4=(f&7)*4
    // B: 1024 float4 total, 4/thread: flat f = tid*4+j, row=f>>5, c4=(f&31)*4
    const int NKB = K >> 5;

    auto load_stage = [&](int kb, int s) {
        const int k0 = kb << 5;
        const uint32_t sA = sbase + s * STAGE_BYTES;
        const uint32_t sB = sA + A_BYTES;
        #pragma unroll
        for (int j = 0; j < 4; ++j) {
            const int f = tid * 4 + j;
            const int r = f >> 3, c = (f & 7) << 2;
            cp16(sA + (uint32_t)r * 144u + (uint32_t)c * 4u,
                 A + (size_t)(m0 + r) * K + k0 + c);
        }
        #pragma unroll
        for (int j = 0; j < 4; ++j) {
            const int f = tid * 4 + j;
            const int r = f >> 5, c = (f & 31) << 2;
            cp16(sB + (uint32_t)r * 544u + (uint32_t)c * 4u,
                 W + (size_t)(k0 + r) * N + n0 + c);
        }
    };

    float acc[2][8][4];
    #pragma unroll
    for (int mt = 0; mt < 2; ++mt)
        #pragma unroll
        for (int nt = 0; nt < 8; ++nt)
            #pragma unroll
            for (int i = 0; i < 4; ++i) acc[mt][nt][i] = 0.f;

    load_stage(0, 0);
    CP_COMMIT();

    for (int kb = 0; kb < NKB; ++kb) {
        const int s = kb & 1;
        if (kb + 1 < NKB) {
            load_stage(kb + 1, s ^ 1);
            CP_COMMIT();
            CP_WAIT(1);
        } else {
            CP_WAIT(0);
        }
        __syncthreads();

        const float* Asf = (const float*)(smem + s * STAGE_BYTES);
        const float* Bsf = (const float*)(smem + s * STAGE_BYTES + A_BYTES);
        const uint32_t* Asu = (const uint32_t*)Asf;
        const uint32_t* Bsu = (const uint32_t*)Bsf;

        #pragma unroll
        for (int ks = 0; ks < 4; ++ks) {
            uint32_t a[2][4], b[8][2];
            const int c = ks * 8 + lc;
            #pragma unroll
            for (int mt = 0; mt < 2; ++mt) {
                const int r = wrow * 32 + mt * 16 + lr;
                a[mt][0] = Asu[r * A_STRIDE + c];
                a[mt][1] = Asu[(r + 8) * A_STRIDE + c];
                a[mt][2] = Asu[r * A_STRIDE + c + 4];
                a[mt][3] = Asu[(r + 8) * A_STRIDE + c + 4];
            }
            #pragma unroll
            for (int nt = 0; nt < 8; ++nt) {
                const int n = wcol * 64 + nt * 8 + lr;
                b[nt][0] = Bsu[c * B_STRIDE + n];
                b[nt][1] = Bsu[(c + 4) * B_STRIDE + n];
            }
            #pragma unroll
            for (int mt = 0; mt < 2; ++mt)
                #pragma unroll
                for (int nt = 0; nt < 8; ++nt)
                    mma_tf32(acc[mt][nt], a[mt], b[nt]);
        }
        __syncthreads();
    }

    // epilogue: bias (+GELU) (+Res), float2 stores per (mt,nt) fragment half
    #pragma unroll
    for (int nt = 0; nt < 8; ++nt) {
        const int col = n0 + wcol * 64 + nt * 8 + lc * 2;
        const float2 bv = *(const float2*)&bias[col];
        #pragma unroll
        for (int mt = 0; mt < 2; ++mt) {
            const int row = m0 + wrow * 32 + mt * 16 + lr;
            #pragma unroll
            for (int half = 0; half < 2; ++half) {
                const int r = row + half * 8;
                float vx = acc[mt][nt][half * 2 + 0] + bv.x;
                float vy = acc[mt][nt][half * 2 + 1] + bv.y;
                if (ACT == 1) {
                    vx = 0.5f * vx * (1.0f + erff(vx * 0.7071067811865475f));
                    vy = 0.5f * vy * (1.0f + erff(vy * 0.7071067811865475f));
                }
                if (HAS_RES) {
                    float2 rv = *(const float2*)&Res[(size_t)r * N + col];
                    vx += rv.x; vy += rv.y;
                }
                float2 o; o.x = vx; o.y = vy;
                *(float2*)&C[(size_t)r * N + col] = o;
            }
        }
    }
}

// ---------------- flash attention (fp32, causal, analytic ALiBi) ----------------
__global__ void __launch_bounds__(256, 2)
attn_kernel(const float* __restrict__ Q, const float* __restrict__ K,
            const float* __restrict__ V, float* __restrict__ O) {
    extern __shared__ float sm[];
    float (*Qs)[65]  = (float(*)[65])sm;
    float (*KVs)[65] = (float(*)[65])(sm + 64 * 65);
    float (*Ss)[65]  = (float(*)[65])(sm + 2 * 64 * 65);
    float* m_sh = sm + 3 * 64 * 65;
    float* l_sh = m_sh + 64;
    float* a_sh = l_sh + 64;

    int qb = blockIdx.x, h = blockIdx.y;
    int tid = threadIdx.x;
    int r0 = (tid >> 4) * 4;
    int c0 = (tid & 15) * 4;

    for (int i = tid; i < 64 * 16; i += 256) {
        int r = i >> 4, c4 = (i & 15) << 2;
        float4 v = *reinterpret_cast<const float4*>(&Q[(size_t)(qb * 64 + r) * D_MODEL + h * 64 + c4]);
        Qs[r][c4] = v.x; Qs[r][c4 + 1] = v.y; Qs[r][c4 + 2] = v.z; Qs[r][c4 + 3] = v.w;
    }
    if (tid < 64) { m_sh[tid] = -1e30f; l_sh[tid] = 0.f; }

    float o_acc[4][4] = {};
    float slope = exp2f(-0.5f * (float)(h + 1));

    for (int kb = 0; kb <= qb; ++kb) {
        __syncthreads();
        for (int i = tid; i < 64 * 16; i += 256) {
            int r = i >> 4, c4 = (i & 15) << 2;
            float4 v = *reinterpret_cast<const float4*>(&K[(size_t)(kb * 64 + r) * D_MODEL + h * 64 + c4]);
            KVs[r][c4] = v.x; KVs[r][c4 + 1] = v.y; KVs[r][c4 + 2] = v.z; KVs[r][c4 + 3] = v.w;
        }
        __syncthreads();

        float s_acc[4][4] = {};
        #pragma unroll
        for (int d = 0; d < 64; ++d) {
            float qv[4], kv[4];
            #pragma unroll
            for (int i = 0; i < 4; ++i) qv[i] = Qs[r0 + i][d];
            #pragma unroll
            for (int j = 0; j < 4; ++j) kv[j] = KVs[c0 + j][d];
            #pragma unroll
            for (int i = 0; i < 4; ++i)
                #pragma unroll
                for (int j = 0; j < 4; ++j)
                    s_acc[i][j] = fmaf(qv[i], kv[j], s_acc[i][j]);
        }
        #pragma unroll
        for (int i = 0; i < 4; ++i) {
            int qq = qb * 64 + r0 + i;
            #pragma unroll
            for (int j = 0; j < 4; ++j) {
                int kk = kb * 64 + c0 + j;
                float v = s_acc[i][j] * 0.125f + slope * (float)(kk - qq);
                Ss[r0 + i][c0 + j] = (kk <= qq) ? v : -1e30f;
            }
        }
        __syncthreads();

        if (tid < 64) {
            float mo = m_sh[tid];
            float mx = mo;
            #pragma unroll 8
            for (int c = 0; c < 64; ++c) mx = fmaxf(mx, Ss[tid][c]);
            float alpha = __expf(mo - mx);
            float sum = 0.f;
            #pragma unroll 8
            for (int c = 0; c < 64; ++c) {
                float p = __expf(Ss[tid][c] - mx);
                Ss[tid][c] = p;
                sum += p;
            }
            m_sh[tid] = mx;
            l_sh[tid] = l_sh[tid] * alpha + sum;
            a_sh[tid] = alpha;
        }
        __syncthreads();

        #pragma unroll
        for (int i = 0; i < 4; ++i) {
            float a = a_sh[r0 + i];
            #pragma unroll
            for (int j = 0; j < 4; ++j) o_acc[i][j] *= a;
        }
        for (int i = tid; i < 64 * 16; i += 256) {
            int r = i >> 4, c4 = (i & 15) << 2;
            float4 v = *reinterpret_cast<const float4*>(&V[(size_t)(kb * 64 + r) * D_MODEL + h * 64 + c4]);
            KVs[r][c4] = v.x; KVs[r][c4 + 1] = v.y; KVs[r][c4 + 2] = v.z; KVs[r][c4 + 3] = v.w;
        }
        __syncthreads();

        #pragma unroll
        for (int k = 0; k < 64; ++k) {
            float pv[4], vv[4];
            #pragma unroll
            for (int i = 0; i < 4; ++i) pv[i] = Ss[r0 + i][k];
            #pragma unroll
            for (int j = 0; j < 4; ++j) vv[j] = KVs[k][c0 + j];
            #pragma unroll
            for (int i = 0; i < 4; ++i)
                #pragma unroll
                for (int j = 0; j < 4; ++j)
                    o_acc[i][j] = fmaf(pv[i], vv[j], o_acc[i][j]);
        }
    }
    __syncthreads();

    #pragma unroll
    for (int i = 0; i < 4; ++i) {
        float inv = 1.f / l_sh[r0 + i];
        int row = qb * 64 + r0 + i;
        #pragma unroll
        for (int j = 0; j < 4; ++j)
            O[(size_t)row * D_MODEL + h * 64 + c0 + j] = o_acc[i][j] * inv;
    }
}

// ---------------- launch ----------------
extern "C" void kernel_launch(void* const* d_in, const int* in_sizes, int n_in,
                              void* d_out, int out_size) {
    const float* x   = (const float*)d_in[0];
    const float* wq  = (const float*)d_in[3];
    const float* bq  = (const float*)d_in[4];
    const float* wk  = (const float*)d_in[5];
    const float* bk  = (const float*)d_in[6];
    const float* wv  = (const float*)d_in[7];
    const float* bv  = (const float*)d_in[8];
    const float* wo  = (const float*)d_in[9];
    const float* bo  = (const float*)d_in[10];
    const float* w1  = (const float*)d_in[11];
    const float* b1  = (const float*)d_in[12];
    const float* w2  = (const float*)d_in[13];
    const float* b2  = (const float*)d_in[14];
    const float* g1  = (const float*)d_in[15];
    const float* be1 = (const float*)d_in[16];
    const float* g2  = (const float*)d_in[17];
    const float* be2 = (const float*)d_in[18];
    float* out = (float*)d_out;

    float *p_xn, *p_q, *p_k, *p_v, *p_attn, *p_x1, *p_h;
    cudaGetSymbolAddress((void**)&p_xn,   g_xn);
    cudaGetSymbolAddress((void**)&p_q,    g_q);
    cudaGetSymbolAddress((void**)&p_k,    g_k);
    cudaGetSymbolAddress((void**)&p_v,    g_v);
    cudaGetSymbolAddress((void**)&p_attn, g_attn);
    cudaGetSymbolAddress((void**)&p_x1,   g_x1);
    cudaGetSymbolAddress((void**)&p_h,    g_h);

    cudaFuncSetAttribute(mma_gemm<0, false>, cudaFuncAttributeMaxDynamicSharedMemorySize, SMEM_GEMM);
    cudaFuncSetAttribute(mma_gemm<0, true>,  cudaFuncAttributeMaxDynamicSharedMemorySize, SMEM_GEMM);
    cudaFuncSetAttribute(mma_gemm<1, false>, cudaFuncAttributeMaxDynamicSharedMemorySize, SMEM_GEMM);

    int attn_smem = (3 * 64 * 65 + 3 * 64) * (int)sizeof(float);
    cudaFuncSetAttribute(attn_kernel, cudaFuncAttributeMaxDynamicSharedMemorySize, attn_smem);

    // LN1
    ln_kernel<<<T_SEQ, 256>>>(x, g1, be1, p_xn);

    // fused QKV
    mma_gemm<0, false><<<dim3(D_MODEL / 128, T_SEQ / 128, 3), 256, SMEM_GEMM>>>(
        p_xn, wq, wk, wv, bq, bk, bv, nullptr, p_q, p_k, p_v, D_MODEL, D_MODEL);

    // attention
    attn_kernel<<<dim3(T_SEQ / 64, N_HEADS), 256, attn_smem>>>(p_q, p_k, p_v, p_attn);

    // O projection + residual
    mma_gemm<0, true><<<dim3(D_MODEL / 128, T_SEQ / 128, 1), 256, SMEM_GEMM>>>(
        p_attn, wo, wo, wo, bo, bo, bo, x, p_x1, p_x1, p_x1, D_MODEL, D_MODEL);

    // LN2
    ln_kernel<<<T_SEQ, 256>>>(p_x1, g2, be2, p_xn);

    // FFN1 + GELU
    mma_gemm<1, false><<<dim3(FFN_DIM / 128, T_SEQ / 128, 1), 256, SMEM_GEMM>>>(
        p_xn, w1, w1, w1, b1, b1, b1, nullptr, p_h, p_h, p_h, FFN_DIM, D_MODEL);

    // FFN2 + residual -> out
    mma_gemm<0, true><<<dim3(D_MODEL / 128, T_SEQ / 128, 1), 256, SMEM_GEMM>>>(
        p_h, w2, w2, w2, b2, b2, b2, p_x1, out, out, out, D_MODEL, FFN_DIM);
}